// round 11
// baseline (speedup 1.0000x reference)
#include <cuda_runtime.h>
#include <cuda_fp16.h>
#include <math.h>

#define N_NODES  50000
#define N_EDGES  800000
#define N_GRAPHS 512
#define TPB      256
#define TROWS    32
#define N_TILES  ((N_NODES + TROWS - 1) / TROWS)

// ---------------- scratch (no allocations allowed) ----------------
// g_h: 32 half2 per row; slot j = feats (2j, 2j+1)
__device__ __align__(16) __half2 g_h[N_NODES * 32];
// g_acc: 32 float2 per row; slot j = feats (2j, 2j+1)
__device__ __align__(16) float2 g_acc[N_NODES * 32];
__device__ int   g_deg[N_NODES];
__device__ int   g_start[N_NODES];
__device__ int   g_fill[N_NODES];
__device__ int   g_csr[N_EDGES];
__device__ float g_pool[N_GRAPHS];
__device__ float g_cnt[N_GRAPHS];
__device__ int   g_total;
__device__ unsigned g_bar_count;
__device__ volatile unsigned g_bar_gen;

// ---------------- shared-memory union (~26KB; 6 blocks/SM fit) ----------------
union SmemU {
    struct { float Xs[TROWS][68]; float Ws[64][68]; float sdv[TROWS]; } gemm;
    struct { int vals[TPB]; int carry; } scan;
};

// ---------------- software grid barrier ----------------
__device__ __forceinline__ void gbar() {
    __syncthreads();
    if (threadIdx.x == 0) {
        __threadfence();
        unsigned gen = g_bar_gen;
        unsigned arrived = atomicAdd(&g_bar_count, 1u) + 1u;
        if (arrived == gridDim.x) {
            g_bar_count = 0u;
            __threadfence();
            g_bar_gen = gen + 1u;
        } else {
            while (g_bar_gen == gen) { __nanosleep(64); }
        }
        __threadfence();
    }
    __syncthreads();
}

// ---------------- GEMM phase: g_h = dv * (input @ W) ----------------
// Tile = 32 rows x 64 cols, 256 threads, thread computes 2x4 (low reg pressure).
template <int LAYER>
__device__ __forceinline__ void gemm_phase(SmemU& sm, const float* __restrict__ X,
                                           const float* __restrict__ W,
                                           const float* __restrict__ bprev) {
    const int tid = threadIdx.x;
    __syncthreads();  // smem union handoff
#pragma unroll
    for (int i = 0; i < 4; ++i) {
        int idx = tid + i * 256;
        int k = idx >> 4, cc = (idx & 15) << 2;
        *(float4*)&sm.gemm.Ws[k][cc] = *(const float4*)(W + k * 64 + cc);
    }
    __syncthreads();

    const int ty = tid >> 4, tx = tid & 15;
    const int r0 = ty * 2, c0 = tx * 4;

    for (int t = blockIdx.x; t < N_TILES; t += gridDim.x) {
        int base = t * TROWS;
        if (tid < TROWS) {
            int row = base + tid;
            sm.gemm.sdv[tid] = (row < N_NODES) ? rsqrtf((float)(g_deg[row] + 1)) : 0.f;
        }
        __syncthreads();

        if (LAYER == 0) {
#pragma unroll
            for (int i = 0; i < 2; ++i) {          // 32x64 floats = 512 float4
                int idx = tid + i * 256;
                int row = idx >> 4, kc = (idx & 15) << 2;
                int grow = base + row;
                float4 v = make_float4(0.f, 0.f, 0.f, 0.f);
                if (grow < N_NODES) v = *(const float4*)(X + (size_t)grow * 64 + kc);
                *(float4*)&sm.gemm.Xs[row][kc] = v;
            }
        } else {
#pragma unroll
            for (int i = 0; i < 4; ++i) {          // 32 rows x 32 slots = 1024
                int idx = tid + i * 256;
                int row = idx >> 5, s = idx & 31;
                int grow = base + row;
                float x0 = 0.f, x1 = 0.f;
                if (grow < N_NODES) {
                    float2 a = g_acc[grow * 32 + s];
                    float dv = sm.gemm.sdv[row];
                    x0 = fmaxf(fmaf(dv, a.x, bprev[2 * s]),     0.f);
                    x1 = fmaxf(fmaf(dv, a.y, bprev[2 * s + 1]), 0.f);
                }
                sm.gemm.Xs[row][2 * s] = x0;
                sm.gemm.Xs[row][2 * s + 1] = x1;
            }
        }
        __syncthreads();

        float acc[2][4] = {};
#pragma unroll 4
        for (int k4 = 0; k4 < 64; k4 += 4) {
            float xr[2][4], wr[4][4];
#pragma unroll
            for (int i = 0; i < 2; ++i) {
                float4 v = *(const float4*)&sm.gemm.Xs[r0 + i][k4];
                xr[i][0] = v.x; xr[i][1] = v.y; xr[i][2] = v.z; xr[i][3] = v.w;
            }
#pragma unroll
            for (int kk = 0; kk < 4; ++kk) {
                float4 v = *(const float4*)&sm.gemm.Ws[k4 + kk][c0];
                wr[kk][0] = v.x; wr[kk][1] = v.y; wr[kk][2] = v.z; wr[kk][3] = v.w;
            }
#pragma unroll
            for (int kk = 0; kk < 4; ++kk)
#pragma unroll
                for (int i = 0; i < 2; ++i)
#pragma unroll
                    for (int j = 0; j < 4; ++j)
                        acc[i][j] = fmaf(xr[i][kk], wr[kk][j], acc[i][j]);
        }

#pragma unroll
        for (int i = 0; i < 2; ++i) {
            int grow = base + r0 + i;
            if (grow < N_NODES) {
                float dv = sm.gemm.sdv[r0 + i];
                __half2 h0 = __floats2half2_rn(acc[i][0] * dv, acc[i][1] * dv);
                __half2 h1 = __floats2half2_rn(acc[i][2] * dv, acc[i][3] * dv);
                unsigned u0 = *reinterpret_cast<unsigned*>(&h0);
                unsigned u1 = *reinterpret_cast<unsigned*>(&h1);
                *reinterpret_cast<uint2*>(&g_h[grow * 32 + 2 * tx]) = make_uint2(u0, u1);
            }
        }
        __syncthreads();  // protect Xs/sdv before next tile
    }
}

// ---------------- aggregation phase: acc[d] = hs[d] + sum_{s in N(d)} hs[s] ----------------
template <bool FINAL>
__device__ __forceinline__ void aggr_phase(const int* __restrict__ batch,
                                           const float* __restrict__ Wl,
                                           const float* __restrict__ b3) {
    int lane = threadIdx.x & 31;
    int wid = (blockIdx.x * blockDim.x + threadIdx.x) >> 5;
    int nw = (gridDim.x * blockDim.x) >> 5;

    for (int node = wid; node < N_NODES; node += nw) {
        float2 self = __half22float2(g_h[node * 32 + lane]);
        float ax = self.x, ay = self.y;

        int beg = __ldg(&g_start[node]);
        int deg = __ldg(&g_deg[node]);
        int end = beg + deg;
        for (int chunk = beg; chunk < end; chunk += 32) {
            int myidx = chunk + lane;
            int s = (myidx < end) ? g_csr[myidx] : 0;
            int n = end - chunk; if (n > 32) n = 32;
            int j = 0;
            for (; j + 8 <= n; j += 8) {
                int si[8];
#pragma unroll
                for (int u = 0; u < 8; ++u) si[u] = __shfl_sync(0xffffffffu, s, j + u);
                float2 f[8];
#pragma unroll
                for (int u = 0; u < 8; ++u) f[u] = __half22float2(g_h[si[u] * 32 + lane]);
#pragma unroll
                for (int u = 0; u < 8; ++u) { ax += f[u].x; ay += f[u].y; }
            }
            for (; j < n; ++j) {
                int sj = __shfl_sync(0xffffffffu, s, j);
                float2 f = __half22float2(g_h[sj * 32 + lane]);
                ax += f.x; ay += f.y;
            }
        }

        if (!FINAL) {
            g_acc[node * 32 + lane] = make_float2(ax, ay);
        } else {
            float dv = rsqrtf((float)(deg + 1));
            float v = fmaf(dv, ax, b3[2 * lane])     * Wl[2 * lane]
                    + fmaf(dv, ay, b3[2 * lane + 1]) * Wl[2 * lane + 1];
#pragma unroll
            for (int off = 16; off > 0; off >>= 1)
                v += __shfl_down_sync(0xffffffffu, v, off);
            if (lane == 0) atomicAdd(&g_pool[batch[node]], v);
        }
    }
}

// ---------------- the single persistent kernel ----------------
__global__ __launch_bounds__(TPB, 6) void k_persist(
    const float* __restrict__ x, const int* __restrict__ src, const int* __restrict__ dst,
    const int* __restrict__ batch,
    const float* __restrict__ W1, const float* __restrict__ b1,
    const float* __restrict__ W2, const float* __restrict__ b2,
    const float* __restrict__ W3, const float* __restrict__ b3,
    const float* __restrict__ Wl, const float* __restrict__ bl,
    float* __restrict__ out)
{
    __shared__ SmemU sm;
    const int tid = threadIdx.x;
    const int gtid = blockIdx.x * TPB + tid;
    const int nthr = gridDim.x * TPB;

    // ---- P0: zero deg/fill/pool/total + per-graph counts (batch sorted -> binsearch) ----
    for (int i = gtid; i < N_NODES; i += nthr) { g_deg[i] = 0; g_fill[i] = 0; }
    for (int i = gtid; i < N_GRAPHS; i += nthr) {
        g_pool[i] = 0.f;
        int a = 0, b = N_NODES;
        while (a < b) { int m = (a + b) >> 1; if (batch[m] < i) a = m + 1; else b = m; }
        int lb = a;
        a = 0; b = N_NODES;
        while (a < b) { int m = (a + b) >> 1; if (batch[m] <= i) a = m + 1; else b = m; }
        g_cnt[i] = (float)(a - lb);
    }
    if (gtid == 0) g_total = 0;
    gbar();

    // ---- P1: in-degree histogram ----
    for (int e = gtid; e < N_EDGES; e += nthr) atomicAdd(&g_deg[dst[e]], 1);
    gbar();

    // ---- P2: CSR row starts. Block-local prefix + one atomic base per block. ----
    {
        int chunk = (N_NODES + gridDim.x - 1) / gridDim.x;
        int lo = blockIdx.x * chunk;
        int hi = lo + chunk; if (hi > N_NODES) hi = N_NODES;
        if (tid == 0) sm.scan.carry = 0;
        __syncthreads();
        if (lo < N_NODES) {
            for (int b0 = lo; b0 < hi; b0 += TPB) {
                int i = b0 + tid;
                int v = (i < hi) ? g_deg[i] : 0;
                sm.scan.vals[tid] = v;
                __syncthreads();
                for (int off = 1; off < TPB; off <<= 1) {
                    int y = (tid >= off) ? sm.scan.vals[tid - off] : 0;
                    __syncthreads();
                    sm.scan.vals[tid] += y;
                    __syncthreads();
                }
                int excl = sm.scan.vals[tid] - v + sm.scan.carry;
                if (i < hi) g_start[i] = excl;
                __syncthreads();
                if (tid == 0) sm.scan.carry += sm.scan.vals[TPB - 1];
                __syncthreads();
            }
        }
        if (tid == 0) {
            int total = (lo < N_NODES) ? sm.scan.carry : 0;
            sm.scan.carry = atomicAdd(&g_total, total);  // reuse as block base
        }
        __syncthreads();
        int base = sm.scan.carry;
        for (int i = lo + tid; i < hi; i += TPB) g_start[i] += base;
    }
    gbar();

    // ---- P3: CSR fill + layer-1 GEMM (independent; no barrier between) ----
    for (int e = gtid; e < N_EDGES; e += nthr) {
        int d = dst[e];
        int pos = g_start[d] + atomicAdd(&g_fill[d], 1);
        g_csr[pos] = src[e];
    }
    gemm_phase<0>(sm, x, W1, nullptr);
    gbar();

    // ---- layers ----
    aggr_phase<false>(nullptr, nullptr, nullptr);
    gbar();
    gemm_phase<1>(sm, nullptr, W2, b1);
    gbar();
    aggr_phase<false>(nullptr, nullptr, nullptr);
    gbar();
    gemm_phase<2>(sm, nullptr, W3, b2);
    gbar();
    aggr_phase<true>(batch, Wl, b3);
    gbar();

    // ---- P9: mean + linear head + sigmoid ----
    for (int g = gtid; g < N_GRAPHS; g += nthr) {
        float c = fmaxf(g_cnt[g], 1.0f);
        float z = g_pool[g] / c + bl[0];
        out[g] = 1.0f / (1.0f + expf(-z));
    }
}

// warmup helper: balanced dummy edges (i % N_NODES) so static-init run is fast
__global__ void k_iota() {
    int i = blockIdx.x * blockDim.x + threadIdx.x;
    if (i < N_EDGES) g_csr[i] = i % N_NODES;
}

// ---------------- static init: carveout + occupancy-sized grid + full warmup ----------------
namespace {
int g_grid = 888;
struct CudaWarmup {
    CudaWarmup() {
        cudaFree(0);
        int dev = 0; cudaGetDevice(&dev);
        int sms = 148;
        cudaDeviceGetAttribute(&sms, cudaDevAttrMultiProcessorCount, dev);
        cudaFuncSetAttribute(k_persist, cudaFuncAttributePreferredSharedMemoryCarveout,
                             cudaSharedmemCarveoutMaxShared);
        int bps = 1;
        cudaOccupancyMaxActiveBlocksPerMultiprocessor(&bps, k_persist, TPB, 0);
        if (bps < 1) bps = 1;
        g_grid = sms * bps;

        void *pcsr = nullptr, *pacc = nullptr, *pdeg = nullptr;
        cudaGetSymbolAddress(&pcsr, g_csr);
        cudaGetSymbolAddress(&pacc, g_acc);
        cudaGetSymbolAddress(&pdeg, g_deg);
        const int*   ip = (const int*)pcsr;   // iota % N_NODES -> valid node ids
        const int*   bp = (const int*)pdeg;   // after P1, deg==16 < N_GRAPHS: valid pool ids
        const float* fp = (const float*)pacc; // 12.8MB zeros: big enough for x/W/b/Wl/bl

        k_iota<<<(N_EDGES + 255) / 256, 256>>>();
        k_persist<<<g_grid, TPB>>>(fp, ip, ip, bp, fp, fp, fp, fp, fp, fp, fp, fp, (float*)pacc);
        cudaDeviceSynchronize();
    }
};
CudaWarmup g_warmup_instance;
}  // namespace

// ---------------- launch: a single kernel ----------------
extern "C" void kernel_launch(void* const* d_in, const int* in_sizes, int n_in,
                              void* d_out, int out_size) {
    const float* x     = (const float*)d_in[0];
    const int*   ei    = (const int*)d_in[1];    // int32 (JAX x64 disabled)
    const int*   batch = (const int*)d_in[2];
    const float* W1 = (const float*)d_in[3];
    const float* b1 = (const float*)d_in[4];
    const float* W2 = (const float*)d_in[5];
    const float* b2 = (const float*)d_in[6];
    const float* W3 = (const float*)d_in[7];
    const float* b3 = (const float*)d_in[8];
    const float* Wl = (const float*)d_in[9];
    const float* bl = (const float*)d_in[10];
    float* out = (float*)d_out;

    k_persist<<<g_grid, TPB>>>(x, ei, ei + N_EDGES, batch,
                               W1, b1, W2, b2, W3, b3, Wl, bl, out);
}

// round 12
// speedup vs baseline: 1.0360x; 1.0360x over previous
#include <cuda_runtime.h>
#include <cuda_fp16.h>
#include <math.h>

#define N_NODES  50000
#define N_EDGES  800000
#define N_GRAPHS 512
#define TPB      256
#define N_TILES  ((N_NODES + 63) / 64)

// ---------------- scratch (no allocations allowed) ----------------
// g_h: 32 half2 per row; slot j = feats (2j, 2j+1)
__device__ __align__(16) __half2 g_h[N_NODES * 32];
// g_acc: 32 float2 per row; slot j = feats (2j, 2j+1)
__device__ __align__(16) float2 g_acc[N_NODES * 32];
__device__ int   g_deg[N_NODES];
__device__ int   g_start[N_NODES];
__device__ int2  g_rng[N_NODES];     // packed (start, deg): one load in aggr
__device__ int   g_fill[N_NODES];
__device__ int   g_csr[N_EDGES];
__device__ float g_pool[N_GRAPHS];
__device__ float g_cnt[N_GRAPHS];
__device__ int   g_total;
__device__ unsigned g_bar_count;
__device__ volatile unsigned g_bar_gen;

// ---------------- shared-memory union (~35KB; 4 blocks/SM) ----------------
union SmemU {
    struct { float Xs[64][68]; float Ws[64][68]; float sdv[64]; } gemm;
    struct { int vals[TPB]; int carry; } scan;
};

// ---------------- software grid barrier ----------------
__device__ __forceinline__ void gbar() {
    __syncthreads();
    if (threadIdx.x == 0) {
        __threadfence();
        unsigned gen = g_bar_gen;
        unsigned arrived = atomicAdd(&g_bar_count, 1u) + 1u;
        if (arrived == gridDim.x) {
            g_bar_count = 0u;
            __threadfence();
            g_bar_gen = gen + 1u;
        } else {
            while (g_bar_gen == gen) { __nanosleep(64); }
        }
        __threadfence();
    }
    __syncthreads();
}

// ---------------- GEMM phase (R10 config: 64-row tile, 4x4 per thread) ----------------
template <int LAYER>
__device__ __forceinline__ void gemm_phase(SmemU& sm, const float* __restrict__ X,
                                           const float* __restrict__ W,
                                           const float* __restrict__ bprev) {
    const int tid = threadIdx.x;
    __syncthreads();  // smem union handoff
#pragma unroll
    for (int i = 0; i < 4; ++i) {
        int idx = tid + i * 256;
        int k = idx >> 4, cc = (idx & 15) << 2;
        *(float4*)&sm.gemm.Ws[k][cc] = *(const float4*)(W + k * 64 + cc);
    }
    __syncthreads();

    const int ty = tid >> 4, tx = tid & 15;
    const int r0 = ty * 4, c0 = tx * 4;

    for (int t = blockIdx.x; t < N_TILES; t += gridDim.x) {
        int base = t * 64;
        if (tid < 64) {
            int row = base + tid;
            sm.gemm.sdv[tid] = (row < N_NODES) ? rsqrtf((float)(g_deg[row] + 1)) : 0.f;
        }
        __syncthreads();

        if (LAYER == 0) {
#pragma unroll
            for (int i = 0; i < 4; ++i) {
                int idx = tid + i * 256;
                int row = idx >> 4, kc = (idx & 15) << 2;
                int grow = base + row;
                float4 v = make_float4(0.f, 0.f, 0.f, 0.f);
                if (grow < N_NODES) v = *(const float4*)(X + (size_t)grow * 64 + kc);
                *(float4*)&sm.gemm.Xs[row][kc] = v;
            }
        } else {
#pragma unroll
            for (int i = 0; i < 8; ++i) {
                int idx = tid + i * 256;       // 2048 = 64 rows x 32 slots
                int row = idx >> 5, s = idx & 31;
                int grow = base + row;
                float x0 = 0.f, x1 = 0.f;
                if (grow < N_NODES) {
                    float2 a = g_acc[grow * 32 + s];
                    float dv = sm.gemm.sdv[row];
                    x0 = fmaxf(fmaf(dv, a.x, bprev[2 * s]),     0.f);
                    x1 = fmaxf(fmaf(dv, a.y, bprev[2 * s + 1]), 0.f);
                }
                sm.gemm.Xs[row][2 * s] = x0;
                sm.gemm.Xs[row][2 * s + 1] = x1;
            }
        }
        __syncthreads();

        float acc[4][4] = {};
#pragma unroll 2
        for (int k4 = 0; k4 < 64; k4 += 4) {
            float xr[4][4], wr[4][4];
#pragma unroll
            for (int i = 0; i < 4; ++i) {
                float4 v = *(const float4*)&sm.gemm.Xs[r0 + i][k4];
                xr[i][0] = v.x; xr[i][1] = v.y; xr[i][2] = v.z; xr[i][3] = v.w;
            }
#pragma unroll
            for (int kk = 0; kk < 4; ++kk) {
                float4 v = *(const float4*)&sm.gemm.Ws[k4 + kk][c0];
                wr[kk][0] = v.x; wr[kk][1] = v.y; wr[kk][2] = v.z; wr[kk][3] = v.w;
            }
#pragma unroll
            for (int kk = 0; kk < 4; ++kk)
#pragma unroll
                for (int i = 0; i < 4; ++i)
#pragma unroll
                    for (int j = 0; j < 4; ++j)
                        acc[i][j] = fmaf(xr[i][kk], wr[kk][j], acc[i][j]);
        }

#pragma unroll
        for (int i = 0; i < 4; ++i) {
            int grow = base + r0 + i;
            if (grow < N_NODES) {
                float dv = sm.gemm.sdv[r0 + i];
                __half2 h0 = __floats2half2_rn(acc[i][0] * dv, acc[i][1] * dv);
                __half2 h1 = __floats2half2_rn(acc[i][2] * dv, acc[i][3] * dv);
                unsigned u0 = *reinterpret_cast<unsigned*>(&h0);
                unsigned u1 = *reinterpret_cast<unsigned*>(&h1);
                *reinterpret_cast<uint2*>(&g_h[grow * 32 + 2 * tx]) = make_uint2(u0, u1);
            }
        }
        __syncthreads();  // protect Xs/sdv before next tile
    }
}

// ---------------- aggregation phase: acc[d] = hs[d] + sum_{s in N(d)} hs[s] ----------------
// Warp per node, software-pipelined across nodes: while gathering node i,
// prefetch node (i+stride)'s packed (start,deg) AND its first chunk of CSR
// indices, hiding the 2-deep pointer chase under the current node's gathers.
template <bool FINAL>
__device__ __forceinline__ void aggr_phase(const int* __restrict__ batch,
                                           const float* __restrict__ Wl,
                                           const float* __restrict__ b3) {
    int lane = threadIdx.x & 31;
    int wid = (blockIdx.x * blockDim.x + threadIdx.x) >> 5;
    int nw = (gridDim.x * blockDim.x) >> 5;

    int node = wid;
    if (node >= N_NODES) return;

    // prologue: fetch first node's range + first-chunk indices
    int2 rng = g_rng[node];
    int s0 = (lane < rng.y) ? g_csr[rng.x + lane] : 0;

    while (node < N_NODES) {
        int nxt = node + nw;
        int2 rng_n = make_int2(0, 0);
        int s0_n = 0;
        if (nxt < N_NODES) {
            rng_n = g_rng[nxt];                                   // prefetch (indep.)
            s0_n = (lane < rng_n.y) ? g_csr[rng_n.x + lane] : 0;  // prefetch chunk 0
        }

        float2 self = __half22float2(g_h[node * 32 + lane]);
        float ax = self.x, ay = self.y;
        int deg = rng.y, beg = rng.x;

        // chunk 0 (preloaded indices)
        {
            int n = deg > 32 ? 32 : deg;
            int j = 0;
            for (; j + 8 <= n; j += 8) {
                int si[8];
#pragma unroll
                for (int u = 0; u < 8; ++u) si[u] = __shfl_sync(0xffffffffu, s0, j + u);
                float2 f[8];
#pragma unroll
                for (int u = 0; u < 8; ++u) f[u] = __half22float2(g_h[si[u] * 32 + lane]);
#pragma unroll
                for (int u = 0; u < 8; ++u) { ax += f[u].x; ay += f[u].y; }
            }
            for (; j < n; ++j) {
                int sj = __shfl_sync(0xffffffffu, s0, j);
                float2 f = __half22float2(g_h[sj * 32 + lane]);
                ax += f.x; ay += f.y;
            }
        }
        // remaining chunks (rare: deg > 32)
        for (int chunk = 32; chunk < deg; chunk += 32) {
            int myidx = chunk + lane;
            int s = (myidx < deg) ? g_csr[beg + myidx] : 0;
            int n = deg - chunk; if (n > 32) n = 32;
            int j = 0;
            for (; j + 8 <= n; j += 8) {
                int si[8];
#pragma unroll
                for (int u = 0; u < 8; ++u) si[u] = __shfl_sync(0xffffffffu, s, j + u);
                float2 f[8];
#pragma unroll
                for (int u = 0; u < 8; ++u) f[u] = __half22float2(g_h[si[u] * 32 + lane]);
#pragma unroll
                for (int u = 0; u < 8; ++u) { ax += f[u].x; ay += f[u].y; }
            }
            for (; j < n; ++j) {
                int sj = __shfl_sync(0xffffffffu, s, j);
                float2 f = __half22float2(g_h[sj * 32 + lane]);
                ax += f.x; ay += f.y;
            }
        }

        if (!FINAL) {
            g_acc[node * 32 + lane] = make_float2(ax, ay);
        } else {
            float dv = rsqrtf((float)(deg + 1));
            float v = fmaf(dv, ax, b3[2 * lane])     * Wl[2 * lane]
                    + fmaf(dv, ay, b3[2 * lane + 1]) * Wl[2 * lane + 1];
#pragma unroll
            for (int off = 16; off > 0; off >>= 1)
                v += __shfl_down_sync(0xffffffffu, v, off);
            if (lane == 0) atomicAdd(&g_pool[batch[node]], v);
        }

        node = nxt; rng = rng_n; s0 = s0_n;
    }
}

// ---------------- the single persistent kernel ----------------
__global__ __launch_bounds__(TPB) void k_persist(
    const float* __restrict__ x, const int* __restrict__ src, const int* __restrict__ dst,
    const int* __restrict__ batch,
    const float* __restrict__ W1, const float* __restrict__ b1,
    const float* __restrict__ W2, const float* __restrict__ b2,
    const float* __restrict__ W3, const float* __restrict__ b3,
    const float* __restrict__ Wl, const float* __restrict__ bl,
    float* __restrict__ out)
{
    __shared__ SmemU sm;
    const int tid = threadIdx.x;
    const int gtid = blockIdx.x * TPB + tid;
    const int nthr = gridDim.x * TPB;

    // ---- P0: zero deg/fill/pool/total + per-graph counts (batch sorted -> binsearch) ----
    for (int i = gtid; i < N_NODES; i += nthr) { g_deg[i] = 0; g_fill[i] = 0; }
    for (int i = gtid; i < N_GRAPHS; i += nthr) {
        g_pool[i] = 0.f;
        int a = 0, b = N_NODES;
        while (a < b) { int m = (a + b) >> 1; if (batch[m] < i) a = m + 1; else b = m; }
        int lb = a;
        a = 0; b = N_NODES;
        while (a < b) { int m = (a + b) >> 1; if (batch[m] <= i) a = m + 1; else b = m; }
        g_cnt[i] = (float)(a - lb);
    }
    if (gtid == 0) g_total = 0;
    gbar();

    // ---- P1: in-degree histogram ----
    for (int e = gtid; e < N_EDGES; e += nthr) atomicAdd(&g_deg[dst[e]], 1);
    gbar();

    // ---- P2: CSR row starts. Block-local prefix + one atomic base per block. ----
    {
        int chunk = (N_NODES + gridDim.x - 1) / gridDim.x;
        int lo = blockIdx.x * chunk;
        int hi = lo + chunk; if (hi > N_NODES) hi = N_NODES;
        if (tid == 0) sm.scan.carry = 0;
        __syncthreads();
        if (lo < N_NODES) {
            for (int b0 = lo; b0 < hi; b0 += TPB) {
                int i = b0 + tid;
                int v = (i < hi) ? g_deg[i] : 0;
                sm.scan.vals[tid] = v;
                __syncthreads();
                for (int off = 1; off < TPB; off <<= 1) {
                    int y = (tid >= off) ? sm.scan.vals[tid - off] : 0;
                    __syncthreads();
                    sm.scan.vals[tid] += y;
                    __syncthreads();
                }
                int excl = sm.scan.vals[tid] - v + sm.scan.carry;
                if (i < hi) g_start[i] = excl;
                __syncthreads();
                if (tid == 0) sm.scan.carry += sm.scan.vals[TPB - 1];
                __syncthreads();
            }
        }
        if (tid == 0) {
            int total = (lo < N_NODES) ? sm.scan.carry : 0;
            sm.scan.carry = atomicAdd(&g_total, total);  // reuse as block base
        }
        __syncthreads();
        int base = sm.scan.carry;
        for (int i = lo + tid; i < hi; i += TPB) {
            int st = g_start[i] + base;
            g_start[i] = st;
            g_rng[i] = make_int2(st, g_deg[i]);   // packed for aggr
        }
    }
    gbar();

    // ---- P3: CSR fill + layer-1 GEMM (independent; no barrier between) ----
    for (int e = gtid; e < N_EDGES; e += nthr) {
        int d = dst[e];
        int pos = g_start[d] + atomicAdd(&g_fill[d], 1);
        g_csr[pos] = src[e];
    }
    gemm_phase<0>(sm, x, W1, nullptr);
    gbar();

    // ---- layers ----
    aggr_phase<false>(nullptr, nullptr, nullptr);
    gbar();
    gemm_phase<1>(sm, nullptr, W2, b1);
    gbar();
    aggr_phase<false>(nullptr, nullptr, nullptr);
    gbar();
    gemm_phase<2>(sm, nullptr, W3, b2);
    gbar();
    aggr_phase<true>(batch, Wl, b3);
    gbar();

    // ---- P9: mean + linear head + sigmoid ----
    for (int g = gtid; g < N_GRAPHS; g += nthr) {
        float c = fmaxf(g_cnt[g], 1.0f);
        float z = g_pool[g] / c + bl[0];
        out[g] = 1.0f / (1.0f + expf(-z));
    }
}

// warmup helper: balanced dummy edges (i % N_NODES) so static-init run is fast
__global__ void k_iota() {
    int i = blockIdx.x * blockDim.x + threadIdx.x;
    if (i < N_EDGES) g_csr[i] = i % N_NODES;
}

// ---------------- static init: carveout + occupancy-sized grid + full warmup ----------------
namespace {
int g_grid = 592;
struct CudaWarmup {
    CudaWarmup() {
        cudaFree(0);
        int dev = 0; cudaGetDevice(&dev);
        int sms = 148;
        cudaDeviceGetAttribute(&sms, cudaDevAttrMultiProcessorCount, dev);
        cudaFuncSetAttribute(k_persist, cudaFuncAttributePreferredSharedMemoryCarveout,
                             cudaSharedmemCarveoutMaxShared);
        int bps = 1;
        cudaOccupancyMaxActiveBlocksPerMultiprocessor(&bps, k_persist, TPB, 0);
        if (bps < 1) bps = 1;
        g_grid = sms * bps;

        void *pcsr = nullptr, *pacc = nullptr, *pdeg = nullptr;
        cudaGetSymbolAddress(&pcsr, g_csr);
        cudaGetSymbolAddress(&pacc, g_acc);
        cudaGetSymbolAddress(&pdeg, g_deg);
        const int*   ip = (const int*)pcsr;   // iota % N_NODES -> valid node ids
        const int*   bp = (const int*)pdeg;   // after P1, deg==16 < N_GRAPHS: valid pool ids
        const float* fp = (const float*)pacc; // 12.8MB zeros: big enough for x/W/b/Wl/bl

        k_iota<<<(N_EDGES + 255) / 256, 256>>>();
        k_persist<<<g_grid, TPB>>>(fp, ip, ip, bp, fp, fp, fp, fp, fp, fp, fp, fp, (float*)pacc);
        cudaDeviceSynchronize();
    }
};
CudaWarmup g_warmup_instance;
}  // namespace

// ---------------- launch: a single kernel ----------------
extern "C" void kernel_launch(void* const* d_in, const int* in_sizes, int n_in,
                              void* d_out, int out_size) {
    const float* x     = (const float*)d_in[0];
    const int*   ei    = (const int*)d_in[1];    // int32 (JAX x64 disabled)
    const int*   batch = (const int*)d_in[2];
    const float* W1 = (const float*)d_in[3];
    const float* b1 = (const float*)d_in[4];
    const float* W2 = (const float*)d_in[5];
    const float* b2 = (const float*)d_in[6];
    const float* W3 = (const float*)d_in[7];
    const float* b3 = (const float*)d_in[8];
    const float* Wl = (const float*)d_in[9];
    const float* bl = (const float*)d_in[10];
    float* out = (float*)d_out;

    k_persist<<<g_grid, TPB>>>(x, ei, ei + N_EDGES, batch,
                               W1, b1, W2, b2, W3, b3, Wl, bl, out);
}